// round 1
// baseline (speedup 1.0000x reference)
#include <cuda_runtime.h>

// Problem constants
#define S_LEN   2048
#define HDIM    64
#define IDIM    32
#define ODIM    32
#define NCHAIN  256                         // B*P = 8*32
#define OBS_N   (NCHAIN * S_LEN * ODIM)     // 16,777,216
#define HID_N   (NCHAIN * S_LEN * HDIM)     // 33,554,432

// ---------------------------------------------------------------------------
// Packed f32x2 helpers (Blackwell FFMA2 path — 2x fp32 FMA throughput)
// ---------------------------------------------------------------------------
__device__ __forceinline__ unsigned long long f2ull(float lo, float hi) {
    unsigned long long r;
    asm("mov.b64 %0, {%1,%2};" : "=l"(r) : "f"(lo), "f"(hi));
    return r;
}
__device__ __forceinline__ void ull2f(unsigned long long u, float& lo, float& hi) {
    asm("mov.b64 {%0,%1}, %2;" : "=f"(lo), "=f"(hi) : "l"(u));
}
__device__ __forceinline__ unsigned long long fma2(unsigned long long a,
                                                   unsigned long long b,
                                                   unsigned long long c) {
    unsigned long long d;
    asm("fma.rn.f32x2 %0, %1, %2, %3;" : "=l"(d) : "l"(a), "l"(b), "l"(c));
    return d;
}

// Fast accurate tanh: 1 - 2/(e^{2x}+1). Handles +-inf saturation correctly.
__device__ __forceinline__ float tanh_fast(float x) {
    float e = __expf(2.0f * x);
    return 1.0f - __fdividef(2.0f, e + 1.0f);
}

// ---------------------------------------------------------------------------
// Kernel 1: pre[r, h] = sum_i x[r, i] * W_ih[h, i] + b_ih[h] + b_hh[h]
// r = flattened (b, p, s) row, 524288 rows. Block = 256 threads handles 32 rows.
// Thread layout: h = tid & 63, rq = tid >> 6 (4 groups of 8 rows each).
// Output written into the HIDDEN region of d_out (consumed in-place by rnn).
// ---------------------------------------------------------------------------
__global__ void __launch_bounds__(256) pre_kernel(
    const float* __restrict__ x,
    const float* __restrict__ W_ih,
    const float* __restrict__ b_ih,
    const float* __restrict__ b_hh,
    float* __restrict__ preout)
{
    const int tid = threadIdx.x;
    const int h   = tid & 63;
    const int rq  = tid >> 6;               // 0..3
    const int row0 = blockIdx.x * 32;       // first global row of this block

    __shared__ float4 xs[32 * 8];           // 32 rows x 32 floats (4 KB)
    __shared__ float  wsh[HDIM * IDIM];     // 64 x 32 row-major (8 KB)

    // Cooperative loads
    const float4* w4 = (const float4*)W_ih;                 // 512 float4
    ((float4*)wsh)[tid]       = w4[tid];
    ((float4*)wsh)[tid + 256] = w4[tid + 256];
    const float4* x4 = (const float4*)(x + (size_t)row0 * IDIM);  // 256 float4
    xs[tid] = x4[tid];
    __syncthreads();

    // This thread's W_ih row as f32x2 pairs in registers
    unsigned long long w2[16];
#pragma unroll
    for (int i = 0; i < 8; i++) {
        float4 v = ((const float4*)(wsh + h * IDIM))[i];
        w2[2 * i]     = f2ull(v.x, v.y);
        w2[2 * i + 1] = f2ull(v.z, v.w);
    }
    const float bias = __ldg(b_ih + h) + __ldg(b_hh + h);

#pragma unroll
    for (int rr = 0; rr < 8; rr++) {
        const int r = rq * 8 + rr;          // row within block
        unsigned long long a0 = 0ull, a1 = 0ull;
#pragma unroll
        for (int i = 0; i < 8; i++) {
            float4 v = xs[r * 8 + i];
            a0 = fma2(f2ull(v.x, v.y), w2[2 * i],     a0);
            a1 = fma2(f2ull(v.z, v.w), w2[2 * i + 1], a1);
        }
        float s0, s1, s2, s3;
        ull2f(a0, s0, s1);
        ull2f(a1, s2, s3);
        preout[(size_t)(row0 + r) * HDIM + h] = (s0 + s1) + (s2 + s3) + bias;
    }
}

// ---------------------------------------------------------------------------
// Kernel 2: recurrence. h_{s} = tanh(pre_s + W_hh * h_{s-1}), h_{-1} = 0.
// One chain per 64 threads (thread t owns output h[t], W_hh row t in regs).
// 2 chains / 128-thread block, grid = 128 blocks -> exactly 1 warp per SMSP.
// pre is read from `hid` and overwritten in place with the hidden state
// (same thread, read-before-write, 4-step prefetch ring -> always safe).
// ---------------------------------------------------------------------------
__global__ void __launch_bounds__(128, 1) rnn_kernel(
    const float* __restrict__ W_hh,
    float* hid,                              // in: pre, out: hidden
    float* __restrict__ h_last)
{
    const int t  = threadIdx.x & 63;         // output index within chain
    const int cl = threadIdx.x >> 6;         // chain slot within block (0/1)
    const int chain = blockIdx.x * 2 + cl;   // 0..255
    float* base = hid + (size_t)chain * S_LEN * HDIM;

    // W_hh row t -> registers as 32 f32x2 pairs
    unsigned long long w2[32];
#pragma unroll
    for (int i = 0; i < 16; i++) {
        float4 v = __ldg((const float4*)(W_hh + t * HDIM) + i);
        w2[2 * i]     = f2ull(v.x, v.y);
        w2[2 * i + 1] = f2ull(v.z, v.w);
    }

    // Double-buffered hidden state in SMEM: [chain][buf][16 float4]
    __shared__ float4 hsh[2][2][16];
    if (t < 16) hsh[cl][0][t] = make_float4(0.f, 0.f, 0.f, 0.f);

    // Prefetch ring for pre (depth 4, hides DRAM latency behind the step)
    float ring[4];
#pragma unroll
    for (int d = 0; d < 4; d++) ring[d] = base[d * HDIM + t];
    __syncthreads();

    const float4* pc = &hsh[cl][0][0];       // current h buffer
    float4*       pn = &hsh[cl][1][0];       // next h buffer
    float hv = 0.f;

#pragma unroll 2
    for (int s = 0; s < S_LEN; s++) {
        const float pre = ring[s & 3];
        int sp = s + 4; if (sp > S_LEN - 1) sp = S_LEN - 1;
        ring[s & 3] = base[sp * HDIM + t];   // prefetch (reads precede writes)

        unsigned long long a0 = 0ull, a1 = 0ull, a2 = 0ull, a3 = 0ull;
#pragma unroll
        for (int q = 0; q < 16; q += 2) {
            float4 v0 = pc[q];
            float4 v1 = pc[q + 1];
            a0 = fma2(f2ull(v0.x, v0.y), w2[2 * q],     a0);
            a1 = fma2(f2ull(v0.z, v0.w), w2[2 * q + 1], a1);
            a2 = fma2(f2ull(v1.x, v1.y), w2[2 * q + 2], a2);
            a3 = fma2(f2ull(v1.z, v1.w), w2[2 * q + 3], a3);
        }
        float s0, s1, s2, s3, s4, s5, s6, s7;
        ull2f(a0, s0, s1); ull2f(a1, s2, s3);
        ull2f(a2, s4, s5); ull2f(a3, s6, s7);
        const float z = ((s0 + s1) + (s2 + s3)) + ((s4 + s5) + (s6 + s7)) + pre;

        hv = tanh_fast(z);
        base[s * HDIM + t] = hv;             // hidden output (overwrites pre)
        ((float*)pn)[t] = hv;                // publish to next buffer
        __syncthreads();
        float4* tmp = (float4*)pc; pc = pn; pn = tmp;
    }
    h_last[chain * HDIM + t] = hv;
}

// ---------------------------------------------------------------------------
// Kernel 3: obs[r, o] = sum_h hidden[r, h] * W_fc[o, h] + b_fc[o]
// Block = 256 threads handles 32 rows; o = tid & 31, rq = tid >> 5 (8 groups,
// 4 rows each). W_fc row in registers as f32x2 pairs.
// ---------------------------------------------------------------------------
__global__ void __launch_bounds__(256) fc_kernel(
    const float* __restrict__ hid,
    const float* __restrict__ W_fc,
    const float* __restrict__ b_fc,
    float* __restrict__ obs)
{
    const int tid = threadIdx.x;
    const int o   = tid & 31;
    const int rq  = tid >> 5;                // 0..7
    const int row0 = blockIdx.x * 32;

    __shared__ float4 hs[32 * 16];           // 32 rows x 64 floats (8 KB)
    __shared__ float  wsh[ODIM * HDIM];      // 32 x 64 row-major (8 KB)

    const float4* w4 = (const float4*)W_fc;                  // 512 float4
    ((float4*)wsh)[tid]       = w4[tid];
    ((float4*)wsh)[tid + 256] = w4[tid + 256];
    const float4* h4 = (const float4*)(hid + (size_t)row0 * HDIM); // 512 float4
    hs[tid]       = h4[tid];
    hs[tid + 256] = h4[tid + 256];
    __syncthreads();

    unsigned long long w2[32];
#pragma unroll
    for (int i = 0; i < 16; i++) {
        float4 v = ((const float4*)(wsh + o * HDIM))[i];
        w2[2 * i]     = f2ull(v.x, v.y);
        w2[2 * i + 1] = f2ull(v.z, v.w);
    }
    const float bias = __ldg(b_fc + o);

#pragma unroll
    for (int rr = 0; rr < 4; rr++) {
        const int r = rq * 4 + rr;           // row within block
        unsigned long long a0 = 0ull, a1 = 0ull, a2 = 0ull, a3 = 0ull;
#pragma unroll
        for (int i = 0; i < 16; i += 2) {
            float4 v0 = hs[r * 16 + i];
            float4 v1 = hs[r * 16 + i + 1];
            a0 = fma2(f2ull(v0.x, v0.y), w2[2 * i],     a0);
            a1 = fma2(f2ull(v0.z, v0.w), w2[2 * i + 1], a1);
            a2 = fma2(f2ull(v1.x, v1.y), w2[2 * i + 2], a2);
            a3 = fma2(f2ull(v1.z, v1.w), w2[2 * i + 3], a3);
        }
        float s0, s1, s2, s3, s4, s5, s6, s7;
        ull2f(a0, s0, s1); ull2f(a1, s2, s3);
        ull2f(a2, s4, s5); ull2f(a3, s6, s7);
        obs[(size_t)(row0 + r) * ODIM + o] =
            ((s0 + s1) + (s2 + s3)) + ((s4 + s5) + (s6 + s7)) + bias;
    }
}

// ---------------------------------------------------------------------------
// Launch. d_out layout: [observations | hidden | h_last] (reference return
// order), fp32: 16,777,216 + 33,554,432 + 16,384 = 50,348,032 elements.
// ---------------------------------------------------------------------------
extern "C" void kernel_launch(void* const* d_in, const int* in_sizes, int n_in,
                              void* d_out, int out_size) {
    const float* x    = (const float*)d_in[0];
    const float* W_ih = (const float*)d_in[1];
    const float* b_ih = (const float*)d_in[2];
    const float* W_hh = (const float*)d_in[3];
    const float* b_hh = (const float*)d_in[4];
    const float* W_fc = (const float*)d_in[5];
    const float* b_fc = (const float*)d_in[6];

    float* obs    = (float*)d_out;
    float* hid    = obs + OBS_N;             // doubles as pre scratch
    float* h_last = hid + HID_N;

    const int rows   = NCHAIN * S_LEN;       // 524288
    const int blocks = rows / 32;            // 16384

    pre_kernel<<<blocks, 256>>>(x, W_ih, b_ih, b_hh, hid);
    rnn_kernel<<<NCHAIN / 2, 128>>>(W_hh, hid, h_last);
    fc_kernel<<<blocks, 256>>>(hid, W_fc, b_fc, obs);
}

// round 2
// speedup vs baseline: 1.3531x; 1.3531x over previous
#include <cuda_runtime.h>

// Problem constants
#define S_LEN   2048
#define HDIM    64
#define IDIM    32
#define ODIM    32
#define NCHAIN  256                         // B*P = 8*32
#define OBS_N   (NCHAIN * S_LEN * ODIM)     // 16,777,216
#define HID_N   (NCHAIN * S_LEN * HDIM)     // 33,554,432

// ---------------------------------------------------------------------------
// Packed f32x2 helpers (Blackwell FFMA2 path)
// ---------------------------------------------------------------------------
__device__ __forceinline__ unsigned long long f2ull(float lo, float hi) {
    unsigned long long r;
    asm("mov.b64 %0, {%1,%2};" : "=l"(r) : "f"(lo), "f"(hi));
    return r;
}
__device__ __forceinline__ void ull2f(unsigned long long u, float& lo, float& hi) {
    asm("mov.b64 {%0,%1}, %2;" : "=f"(lo), "=f"(hi) : "l"(u));
}
__device__ __forceinline__ unsigned long long fma2(unsigned long long a,
                                                   unsigned long long b,
                                                   unsigned long long c) {
    unsigned long long d;
    asm("fma.rn.f32x2 %0, %1, %2, %3;" : "=l"(d) : "l"(a), "l"(b), "l"(c));
    return d;
}

// tanh(x) = 1 - 2/(e^{2x}+1); ex2 + rcp.approx + one FFMA on the tail.
__device__ __forceinline__ float tanh_fast(float x) {
    float e;
    asm("ex2.approx.f32 %0, %1;" : "=f"(e) : "f"(x * 2.8853900817779268f)); // 2*log2(e)
    float d = e + 1.0f;
    float r;
    asm("rcp.approx.f32 %0, %1;" : "=f"(r) : "f"(d));
    return fmaf(-2.0f, r, 1.0f);
}

// ---------------------------------------------------------------------------
// Kernel 1: pre[r,h] = sum_i x[r,i]*W_ih[h,i] + b_ih[h] + b_hh[h]
// 128 rows per block of 256 threads. h = tid&63, rq = tid>>6 -> 32 rows each.
// W row read straight from global (8KB, L1-resident); x tiled in smem,
// broadcast reads (same row across a warp).
// ---------------------------------------------------------------------------
__global__ void __launch_bounds__(256) pre_kernel(
    const float* __restrict__ x,
    const float* __restrict__ W_ih,
    const float* __restrict__ b_ih,
    const float* __restrict__ b_hh,
    float* __restrict__ preout)
{
    const int tid = threadIdx.x;
    const int h   = tid & 63;
    const int rq  = tid >> 6;                // 0..3
    const int row0 = blockIdx.x * 128;

    __shared__ float4 xs[128 * 8];           // 128 rows x 32 floats = 16 KB

    const float4* x4 = (const float4*)(x + (size_t)row0 * IDIM); // 1024 float4
#pragma unroll
    for (int j = 0; j < 4; j++) xs[tid + j * 256] = x4[tid + j * 256];

    // W_ih row h -> registers (16 f32x2)
    unsigned long long w2[16];
#pragma unroll
    for (int i = 0; i < 8; i++) {
        float4 v = __ldg((const float4*)(W_ih + h * IDIM) + i);
        w2[2 * i]     = f2ull(v.x, v.y);
        w2[2 * i + 1] = f2ull(v.z, v.w);
    }
    const float bias = __ldg(b_ih + h) + __ldg(b_hh + h);
    __syncthreads();

#pragma unroll 4
    for (int rr = 0; rr < 32; rr++) {
        const int r = rq * 32 + rr;
        unsigned long long a0 = 0ull, a1 = 0ull, a2 = 0ull, a3 = 0ull;
#pragma unroll
        for (int i = 0; i < 8; i += 2) {
            float4 v0 = xs[r * 8 + i];
            float4 v1 = xs[r * 8 + i + 1];
            a0 = fma2(f2ull(v0.x, v0.y), w2[2 * i],     a0);
            a1 = fma2(f2ull(v0.z, v0.w), w2[2 * i + 1], a1);
            a2 = fma2(f2ull(v1.x, v1.y), w2[2 * i + 2], a2);
            a3 = fma2(f2ull(v1.z, v1.w), w2[2 * i + 3], a3);
        }
        float s0, s1, s2, s3, s4, s5, s6, s7;
        ull2f(a0, s0, s1); ull2f(a1, s2, s3);
        ull2f(a2, s4, s5); ull2f(a3, s6, s7);
        preout[(size_t)(row0 + r) * HDIM + h] =
            ((s0 + s1) + (s2 + s3)) + ((s4 + s5) + (s6 + s7)) + bias;
    }
}

// ---------------------------------------------------------------------------
// Kernel 2: recurrence h_s = tanh(pre_s + W_hh h_{s-1}).
// 2 chains per 128-thread block, thread t owns output h[t] (W row in regs).
// Unroll-8 steps: register prefetch ring (compile-time indices -> no local
// memory), depth 8 covers DRAM latency. Double-buffered h in smem (broadcast
// LDS). pre read from `hid` and overwritten in place with hidden.
// ---------------------------------------------------------------------------
__global__ void __launch_bounds__(128, 1) rnn_kernel(
    const float* __restrict__ W_hh,
    float* hid,                              // in: pre, out: hidden
    float* __restrict__ h_last)
{
    const int t  = threadIdx.x & 63;
    const int cl = threadIdx.x >> 6;
    const int chain = blockIdx.x * 2 + cl;
    float* base = hid + (size_t)chain * S_LEN * HDIM;

    // W_hh row t -> 32 f32x2 pairs
    unsigned long long w2[32];
#pragma unroll
    for (int i = 0; i < 16; i++) {
        float4 v = __ldg((const float4*)(W_hh + t * HDIM) + i);
        w2[2 * i]     = f2ull(v.x, v.y);
        w2[2 * i + 1] = f2ull(v.z, v.w);
    }

    __shared__ float4 hsh[2][2][16];         // [chain][buf][16 float4]
    if (t < 16) hsh[cl][0][t] = make_float4(0.f, 0.f, 0.f, 0.f);

    // Register prefetch ring, depth 8 (all indices compile-time constant)
    float ring[8];
#pragma unroll
    for (int d = 0; d < 8; d++) ring[d] = base[d * HDIM + t];
    __syncthreads();

    float hv = 0.f;

    for (int sb = 0; sb < S_LEN; sb += 8) {
#pragma unroll
        for (int k = 0; k < 8; k++) {
            const int s = sb + k;
            const float pre = ring[k];
            int sp = sb + 8 + k;
            if (sp > S_LEN - 1) sp = S_LEN - 1;
            ring[k] = base[(size_t)sp * HDIM + t];   // prefetch next chunk

            const float4* pc = &hsh[cl][k & 1][0];
            // 8 accumulators: dep chain of 4 fma2 each; pre folded into a0
            unsigned long long a0 = f2ull(pre, 0.f), a1 = 0ull, a2 = 0ull, a3 = 0ull,
                               a4 = 0ull, a5 = 0ull, a6 = 0ull, a7 = 0ull;
#pragma unroll
            for (int q = 0; q < 16; q += 4) {
                float4 v0 = pc[q];
                float4 v1 = pc[q + 1];
                float4 v2 = pc[q + 2];
                float4 v3 = pc[q + 3];
                a0 = fma2(f2ull(v0.x, v0.y), w2[2 * q],     a0);
                a1 = fma2(f2ull(v0.z, v0.w), w2[2 * q + 1], a1);
                a2 = fma2(f2ull(v1.x, v1.y), w2[2 * q + 2], a2);
                a3 = fma2(f2ull(v1.z, v1.w), w2[2 * q + 3], a3);
                a4 = fma2(f2ull(v2.x, v2.y), w2[2 * q + 4], a4);
                a5 = fma2(f2ull(v2.z, v2.w), w2[2 * q + 5], a5);
                a6 = fma2(f2ull(v3.x, v3.y), w2[2 * q + 6], a6);
                a7 = fma2(f2ull(v3.z, v3.w), w2[2 * q + 7], a7);
            }
            unsigned long long b0 = a0, b1 = a1, b2 = a2, b3 = a3;
            // pairwise combine in packed form first (4 f32x2 adds via fma2 w/ 1.0)
            float p0, p1, p2, p3, p4, p5, p6, p7;
            float q0, q1, q2, q3, q4, q5, q6, q7;
            ull2f(b0, p0, p1); ull2f(b1, p2, p3);
            ull2f(b2, p4, p5); ull2f(b3, p6, p7);
            ull2f(a4, q0, q1); ull2f(a5, q2, q3);
            ull2f(a6, q4, q5); ull2f(a7, q6, q7);
            const float z = (((p0 + p1) + (p2 + p3)) + ((p4 + p5) + (p6 + p7)))
                          + (((q0 + q1) + (q2 + q3)) + ((q4 + q5) + (q6 + q7)));

            hv = tanh_fast(z);
            base[(size_t)s * HDIM + t] = hv;           // hidden output
            ((float*)&hsh[cl][(k + 1) & 1][0])[t] = hv; // publish next buffer
            __syncthreads();
        }
    }
    h_last[chain * HDIM + t] = hv;
}

// ---------------------------------------------------------------------------
// Kernel 3: obs[r,o] = sum_h hidden[r,h]*W_fc[o,h] + b_fc[o]
// 64 rows per block of 256 threads. o = tid&31, rq = tid>>5 -> 8 rows each.
// W_fc row straight from global (8KB, L1-resident); hidden tile in smem,
// broadcast reads.
// ---------------------------------------------------------------------------
__global__ void __launch_bounds__(256) fc_kernel(
    const float* __restrict__ hid,
    const float* __restrict__ W_fc,
    const float* __restrict__ b_fc,
    float* __restrict__ obs)
{
    const int tid = threadIdx.x;
    const int o   = tid & 31;
    const int rq  = tid >> 5;                // 0..7
    const int row0 = blockIdx.x * 64;

    __shared__ float4 hs[64 * 16];           // 64 rows x 64 floats = 16 KB

    const float4* h4 = (const float4*)(hid + (size_t)row0 * HDIM); // 1024 f4
#pragma unroll
    for (int j = 0; j < 4; j++) hs[tid + j * 256] = h4[tid + j * 256];

    unsigned long long w2[32];
#pragma unroll
    for (int i = 0; i < 16; i++) {
        float4 v = __ldg((const float4*)(W_fc + o * HDIM) + i);
        w2[2 * i]     = f2ull(v.x, v.y);
        w2[2 * i + 1] = f2ull(v.z, v.w);
    }
    const float bias = __ldg(b_fc + o);
    __syncthreads();

#pragma unroll 2
    for (int rr = 0; rr < 8; rr++) {
        const int r = rq * 8 + rr;
        unsigned long long a0 = 0ull, a1 = 0ull, a2 = 0ull, a3 = 0ull;
#pragma unroll
        for (int i = 0; i < 16; i += 2) {
            float4 v0 = hs[r * 16 + i];
            float4 v1 = hs[r * 16 + i + 1];
            a0 = fma2(f2ull(v0.x, v0.y), w2[2 * i],     a0);
            a1 = fma2(f2ull(v0.z, v0.w), w2[2 * i + 1], a1);
            a2 = fma2(f2ull(v1.x, v1.y), w2[2 * i + 2], a2);
            a3 = fma2(f2ull(v1.z, v1.w), w2[2 * i + 3], a3);
        }
        float s0, s1, s2, s3, s4, s5, s6, s7;
        ull2f(a0, s0, s1); ull2f(a1, s2, s3);
        ull2f(a2, s4, s5); ull2f(a3, s6, s7);
        obs[(size_t)(row0 + r) * ODIM + o] =
            ((s0 + s1) + (s2 + s3)) + ((s4 + s5) + (s6 + s7)) + bias;
    }
}

// ---------------------------------------------------------------------------
// Launch. d_out layout: [observations | hidden | h_last], fp32.
// ---------------------------------------------------------------------------
extern "C" void kernel_launch(void* const* d_in, const int* in_sizes, int n_in,
                              void* d_out, int out_size) {
    const float* x    = (const float*)d_in[0];
    const float* W_ih = (const float*)d_in[1];
    const float* b_ih = (const float*)d_in[2];
    const float* W_hh = (const float*)d_in[3];
    const float* b_hh = (const float*)d_in[4];
    const float* W_fc = (const float*)d_in[5];
    const float* b_fc = (const float*)d_in[6];

    float* obs    = (float*)d_out;
    float* hid    = obs + OBS_N;             // doubles as pre scratch
    float* h_last = hid + HID_N;

    const int rows = NCHAIN * S_LEN;         // 524288

    pre_kernel<<<rows / 128, 256>>>(x, W_ih, b_ih, b_hh, hid);
    rnn_kernel<<<NCHAIN / 2, 128>>>(W_hh, hid, h_last);
    fc_kernel<<<rows / 64, 256>>>(hid, W_fc, b_fc, obs);
}

// round 3
// speedup vs baseline: 1.4781x; 1.0924x over previous
#include <cuda_runtime.h>

// Problem constants
#define S_LEN   2048
#define HDIM    64
#define IDIM    32
#define ODIM    32
#define NCHAIN  256                         // B*P = 8*32
#define OBS_N   (NCHAIN * S_LEN * ODIM)     // 16,777,216
#define HID_N   (NCHAIN * S_LEN * HDIM)     // 33,554,432

typedef unsigned long long ull;

// ---------------------------------------------------------------------------
// Packed f32x2 helpers (Blackwell FFMA2 path)
// ---------------------------------------------------------------------------
__device__ __forceinline__ ull f2ull(float lo, float hi) {
    ull r;
    asm("mov.b64 %0, {%1,%2};" : "=l"(r) : "f"(lo), "f"(hi));
    return r;
}
__device__ __forceinline__ void ull2f(ull u, float& lo, float& hi) {
    asm("mov.b64 {%0,%1}, %2;" : "=f"(lo), "=f"(hi) : "l"(u));
}
__device__ __forceinline__ ull fma2(ull a, ull b, ull c) {
    ull d;
    asm("fma.rn.f32x2 %0, %1, %2, %3;" : "=l"(d) : "l"(a), "l"(b), "l"(c));
    return d;
}
__device__ __forceinline__ ull add2(ull a, ull b) {
    ull d;
    asm("add.rn.f32x2 %0, %1, %2;" : "=l"(d) : "l"(a), "l"(b));
    return d;
}

// tanh(x) = 1 - 2/(e^{2x}+1); ex2 + rcp.approx + one FFMA tail.
__device__ __forceinline__ float tanh_fast(float x) {
    float e;
    asm("ex2.approx.f32 %0, %1;" : "=f"(e) : "f"(x * 2.8853900817779268f)); // 2*log2(e)
    float d = e + 1.0f;
    float r;
    asm("rcp.approx.f32 %0, %1;" : "=f"(r) : "f"(d));
    return fmaf(-2.0f, r, 1.0f);
}

// ---------------------------------------------------------------------------
// Kernel 1: pre[r,h] = sum_i x[r,i]*W_ih[h,i] + b_ih[h] + b_hh[h]
// 128 rows / block of 256 threads. Each thread owns an h PAIR (2*h2, 2*h2+1)
// -> 8 LDS.128 per row feed 2 outputs (L1 wavefronts per output halved).
// Output: float2 store. W rows live in registers.
// ---------------------------------------------------------------------------
__global__ void __launch_bounds__(256) pre_kernel(
    const float* __restrict__ x,
    const float* __restrict__ W_ih,
    const float* __restrict__ b_ih,
    const float* __restrict__ b_hh,
    float* __restrict__ preout)
{
    const int tid = threadIdx.x;
    const int h2  = tid & 31;                // h pair = (2*h2, 2*h2+1)
    const int rg  = tid >> 5;                // 0..7, 16 rows each
    const int row0 = blockIdx.x * 128;

    __shared__ float4 xs[128 * 8];           // 128 rows x 32 floats = 16 KB

    const float4* x4 = (const float4*)(x + (size_t)row0 * IDIM); // 1024 f4
#pragma unroll
    for (int j = 0; j < 4; j++) xs[tid + j * 256] = x4[tid + j * 256];

    const int ha = 2 * h2, hb = 2 * h2 + 1;
    ull wa[16], wb[16];
#pragma unroll
    for (int i = 0; i < 8; i++) {
        float4 va = __ldg((const float4*)(W_ih + ha * IDIM) + i);
        float4 vb = __ldg((const float4*)(W_ih + hb * IDIM) + i);
        wa[2 * i]     = f2ull(va.x, va.y);
        wa[2 * i + 1] = f2ull(va.z, va.w);
        wb[2 * i]     = f2ull(vb.x, vb.y);
        wb[2 * i + 1] = f2ull(vb.z, vb.w);
    }
    const float biasA = __ldg(b_ih + ha) + __ldg(b_hh + ha);
    const float biasB = __ldg(b_ih + hb) + __ldg(b_hh + hb);
    __syncthreads();

    float2* out2 = (float2*)preout;

#pragma unroll 2
    for (int rr = 0; rr < 16; rr++) {
        const int r = rg * 16 + rr;
        // Batch the 8 LDS.128 up front (MLP)
        float4 v0 = xs[r * 8 + 0], v1 = xs[r * 8 + 1];
        float4 v2 = xs[r * 8 + 2], v3 = xs[r * 8 + 3];
        float4 v4 = xs[r * 8 + 4], v5 = xs[r * 8 + 5];
        float4 v6 = xs[r * 8 + 6], v7 = xs[r * 8 + 7];
        ull p0 = f2ull(v0.x, v0.y), p1 = f2ull(v0.z, v0.w);
        ull p2 = f2ull(v1.x, v1.y), p3 = f2ull(v1.z, v1.w);
        ull p4 = f2ull(v2.x, v2.y), p5 = f2ull(v2.z, v2.w);
        ull p6 = f2ull(v3.x, v3.y), p7 = f2ull(v3.z, v3.w);
        ull p8 = f2ull(v4.x, v4.y), p9 = f2ull(v4.z, v4.w);
        ull pa = f2ull(v5.x, v5.y), pb = f2ull(v5.z, v5.w);
        ull pc_ = f2ull(v6.x, v6.y), pd = f2ull(v6.z, v6.w);
        ull pe = f2ull(v7.x, v7.y), pf = f2ull(v7.z, v7.w);

        ull aA0 = 0, aA1 = 0, aA2 = 0, aA3 = 0;
        ull aB0 = 0, aB1 = 0, aB2 = 0, aB3 = 0;
        aA0 = fma2(p0, wa[0],  aA0); aB0 = fma2(p0, wb[0],  aB0);
        aA1 = fma2(p1, wa[1],  aA1); aB1 = fma2(p1, wb[1],  aB1);
        aA2 = fma2(p2, wa[2],  aA2); aB2 = fma2(p2, wb[2],  aB2);
        aA3 = fma2(p3, wa[3],  aA3); aB3 = fma2(p3, wb[3],  aB3);
        aA0 = fma2(p4, wa[4],  aA0); aB0 = fma2(p4, wb[4],  aB0);
        aA1 = fma2(p5, wa[5],  aA1); aB1 = fma2(p5, wb[5],  aB1);
        aA2 = fma2(p6, wa[6],  aA2); aB2 = fma2(p6, wb[6],  aB2);
        aA3 = fma2(p7, wa[7],  aA3); aB3 = fma2(p7, wb[7],  aB3);
        aA0 = fma2(p8, wa[8],  aA0); aB0 = fma2(p8, wb[8],  aB0);
        aA1 = fma2(p9, wa[9],  aA1); aB1 = fma2(p9, wb[9],  aB1);
        aA2 = fma2(pa, wa[10], aA2); aB2 = fma2(pa, wb[10], aB2);
        aA3 = fma2(pb, wa[11], aA3); aB3 = fma2(pb, wb[11], aB3);
        aA0 = fma2(pc_, wa[12], aA0); aB0 = fma2(pc_, wb[12], aB0);
        aA1 = fma2(pd, wa[13], aA1); aB1 = fma2(pd, wb[13], aB1);
        aA2 = fma2(pe, wa[14], aA2); aB2 = fma2(pe, wb[14], aB2);
        aA3 = fma2(pf, wa[15], aA3); aB3 = fma2(pf, wb[15], aB3);

        ull uA = add2(add2(aA0, aA1), add2(aA2, aA3));
        ull uB = add2(add2(aB0, aB1), add2(aB2, aB3));
        float la, ha_, lb, hb_;
        ull2f(uA, la, ha_); ull2f(uB, lb, hb_);
        out2[(size_t)(row0 + r) * 32 + h2] =
            make_float2((la + ha_) + biasA, (lb + hb_) + biasB);
    }
}

// ---------------------------------------------------------------------------
// Kernel 2: recurrence h_s = tanh(pre_s + W_hh h_{s-1}).
// ONE chain per 64-thread block (grid 256): 2-warp barrier, no cross-chain
// coupling. Thread t owns output h[t], W row in regs. Unroll-4 with reg
// prefetch ring. LDS of h done in two explicit batches of 8 (caps exposed
// latency at ~2x29 instead of 16x29). Packed f32x2 reduction.
// ---------------------------------------------------------------------------
__global__ void __launch_bounds__(64, 1) rnn_kernel(
    const float* __restrict__ W_hh,
    float* hid,                              // in: pre, out: hidden
    float* __restrict__ h_last)
{
    const int t = threadIdx.x;
    const int chain = blockIdx.x;
    float* base = hid + (size_t)chain * (S_LEN * HDIM);

    ull w2[32];
#pragma unroll
    for (int i = 0; i < 16; i++) {
        float4 v = __ldg((const float4*)(W_hh + t * HDIM) + i);
        w2[2 * i]     = f2ull(v.x, v.y);
        w2[2 * i + 1] = f2ull(v.z, v.w);
    }

    __shared__ float4 hsh[2][16];            // double-buffered h
    if (t < 16) hsh[0][t] = make_float4(0.f, 0.f, 0.f, 0.f);

    float ring[4];
#pragma unroll
    for (int d = 0; d < 4; d++) ring[d] = base[d * HDIM + t];
    __syncthreads();

    float hv = 0.f;

    for (int sb = 0; sb < S_LEN; sb += 4) {
#pragma unroll
        for (int k = 0; k < 4; k++) {
            const int s = sb + k;
            const float pre = ring[k];
            // Prefetch 4 ahead. May overrun chain end by <=4 rows on the last
            // block; stays inside d_out (h_last region), values never consumed.
            ring[k] = base[(size_t)(s + 4) * HDIM + t];

            const float4* pc = hsh[k & 1];

            ull a0 = 0, a1 = 0, a2 = 0, a3 = 0, a4 = 0, a5 = 0, a6 = 0, a7 = 0;

            // ---- batch 1: h[0..31] ----
            {
                float4 v0 = pc[0], v1 = pc[1], v2 = pc[2], v3 = pc[3];
                float4 v4 = pc[4], v5 = pc[5], v6 = pc[6], v7 = pc[7];
                a0 = fma2(f2ull(v0.x, v0.y), w2[0],  a0);
                a1 = fma2(f2ull(v0.z, v0.w), w2[1],  a1);
                a2 = fma2(f2ull(v1.x, v1.y), w2[2],  a2);
                a3 = fma2(f2ull(v1.z, v1.w), w2[3],  a3);
                a4 = fma2(f2ull(v2.x, v2.y), w2[4],  a4);
                a5 = fma2(f2ull(v2.z, v2.w), w2[5],  a5);
                a6 = fma2(f2ull(v3.x, v3.y), w2[6],  a6);
                a7 = fma2(f2ull(v3.z, v3.w), w2[7],  a7);
                a0 = fma2(f2ull(v4.x, v4.y), w2[8],  a0);
                a1 = fma2(f2ull(v4.z, v4.w), w2[9],  a1);
                a2 = fma2(f2ull(v5.x, v5.y), w2[10], a2);
                a3 = fma2(f2ull(v5.z, v5.w), w2[11], a3);
                a4 = fma2(f2ull(v6.x, v6.y), w2[12], a4);
                a5 = fma2(f2ull(v6.z, v6.w), w2[13], a5);
                a6 = fma2(f2ull(v7.x, v7.y), w2[14], a6);
                a7 = fma2(f2ull(v7.z, v7.w), w2[15], a7);
            }
            // ---- batch 2: h[32..63] ----
            {
                float4 v0 = pc[8],  v1 = pc[9],  v2 = pc[10], v3 = pc[11];
                float4 v4 = pc[12], v5 = pc[13], v6 = pc[14], v7 = pc[15];
                a0 = fma2(f2ull(v0.x, v0.y), w2[16], a0);
                a1 = fma2(f2ull(v0.z, v0.w), w2[17], a1);
                a2 = fma2(f2ull(v1.x, v1.y), w2[18], a2);
                a3 = fma2(f2ull(v1.z, v1.w), w2[19], a3);
                a4 = fma2(f2ull(v2.x, v2.y), w2[20], a4);
                a5 = fma2(f2ull(v2.z, v2.w), w2[21], a5);
                a6 = fma2(f2ull(v3.x, v3.y), w2[22], a6);
                a7 = fma2(f2ull(v3.z, v3.w), w2[23], a7);
                a0 = fma2(f2ull(v4.x, v4.y), w2[24], a0);
                a1 = fma2(f2ull(v4.z, v4.w), w2[25], a1);
                a2 = fma2(f2ull(v5.x, v5.y), w2[26], a2);
                a3 = fma2(f2ull(v5.z, v5.w), w2[27], a3);
                a4 = fma2(f2ull(v6.x, v6.y), w2[28], a4);
                a5 = fma2(f2ull(v6.z, v6.w), w2[29], a5);
                a6 = fma2(f2ull(v7.x, v7.y), w2[30], a6);
                a7 = fma2(f2ull(v7.z, v7.w), w2[31], a7);
            }

            // Packed reduction tree (depth 3), then unpack once.
            ull u = add2(add2(add2(a0, a1), add2(a2, a3)),
                         add2(add2(a4, a5), add2(a6, a7)));
            float lo, hi;
            ull2f(u, lo, hi);
            const float z = (lo + hi) + pre;

            hv = tanh_fast(z);
            base[(size_t)s * HDIM + t] = hv;            // hidden output
            ((float*)hsh[(k + 1) & 1])[t] = hv;         // publish next buffer
            __syncthreads();
        }
    }
    h_last[chain * HDIM + t] = hv;
}

// ---------------------------------------------------------------------------
// Kernel 3: obs[r,o] = sum_h hidden[r,h]*W_fc[o,h] + b_fc[o]
// 64 rows / block of 256 threads; o = tid&31, 8 rows per thread group.
// ---------------------------------------------------------------------------
__global__ void __launch_bounds__(256) fc_kernel(
    const float* __restrict__ hid,
    const float* __restrict__ W_fc,
    const float* __restrict__ b_fc,
    float* __restrict__ obs)
{
    const int tid = threadIdx.x;
    const int o   = tid & 31;
    const int rq  = tid >> 5;                // 0..7
    const int row0 = blockIdx.x * 64;

    __shared__ float4 hs[64 * 16];           // 64 rows x 64 floats = 16 KB

    const float4* h4 = (const float4*)(hid + (size_t)row0 * HDIM); // 1024 f4
#pragma unroll
    for (int j = 0; j < 4; j++) hs[tid + j * 256] = h4[tid + j * 256];

    ull w2[32];
#pragma unroll
    for (int i = 0; i < 16; i++) {
        float4 v = __ldg((const float4*)(W_fc + o * HDIM) + i);
        w2[2 * i]     = f2ull(v.x, v.y);
        w2[2 * i + 1] = f2ull(v.z, v.w);
    }
    const float bias = __ldg(b_fc + o);
    __syncthreads();

#pragma unroll 2
    for (int rr = 0; rr < 8; rr++) {
        const int r = rq * 8 + rr;
        ull a0 = 0, a1 = 0, a2 = 0, a3 = 0;
#pragma unroll
        for (int i = 0; i < 16; i += 2) {
            float4 v0 = hs[r * 16 + i];
            float4 v1 = hs[r * 16 + i + 1];
            a0 = fma2(f2ull(v0.x, v0.y), w2[2 * i],     a0);
            a1 = fma2(f2ull(v0.z, v0.w), w2[2 * i + 1], a1);
            a2 = fma2(f2ull(v1.x, v1.y), w2[2 * i + 2], a2);
            a3 = fma2(f2ull(v1.z, v1.w), w2[2 * i + 3], a3);
        }
        ull u = add2(add2(a0, a1), add2(a2, a3));
        float lo, hi;
        ull2f(u, lo, hi);
        obs[(size_t)(row0 + r) * ODIM + o] = (lo + hi) + bias;
    }
}

// ---------------------------------------------------------------------------
// Launch. d_out layout: [observations | hidden | h_last], fp32.
// ---------------------------------------------------------------------------
extern "C" void kernel_launch(void* const* d_in, const int* in_sizes, int n_in,
                              void* d_out, int out_size) {
    const float* x    = (const float*)d_in[0];
    const float* W_ih = (const float*)d_in[1];
    const float* b_ih = (const float*)d_in[2];
    const float* W_hh = (const float*)d_in[3];
    const float* b_hh = (const float*)d_in[4];
    const float* W_fc = (const float*)d_in[5];
    const float* b_fc = (const float*)d_in[6];

    float* obs    = (float*)d_out;
    float* hid    = obs + OBS_N;             // doubles as pre scratch
    float* h_last = hid + HID_N;

    const int rows = NCHAIN * S_LEN;         // 524288

    pre_kernel<<<rows / 128, 256>>>(x, W_ih, b_ih, b_hh, hid);
    rnn_kernel<<<NCHAIN, 64>>>(W_hh, hid, h_last);
    fc_kernel<<<rows / 64, 256>>>(hid, W_fc, b_fc, obs);
}

// round 4
// speedup vs baseline: 2.0060x; 1.3571x over previous
#include <cuda_runtime.h>
#include <cstdint>

// Problem constants
#define S_LEN   2048
#define HDIM    64
#define IDIM    32
#define ODIM    32
#define NCHAIN  256                         // B*P = 8*32
#define OBS_N   (NCHAIN * S_LEN * ODIM)     // 16,777,216
#define HID_N   (NCHAIN * S_LEN * HDIM)     // 33,554,432
#define CHUNK   16
#define NCHUNK  (S_LEN / CHUNK)             // 128

typedef unsigned long long ull;

// ---------------------------------------------------------------------------
// Packed f32x2 helpers (Blackwell FFMA2 path)
// ---------------------------------------------------------------------------
__device__ __forceinline__ ull f2ull(float lo, float hi) {
    ull r;
    asm("mov.b64 %0, {%1,%2};" : "=l"(r) : "f"(lo), "f"(hi));
    return r;
}
__device__ __forceinline__ void ull2f(ull u, float& lo, float& hi) {
    asm("mov.b64 {%0,%1}, %2;" : "=f"(lo), "=f"(hi) : "l"(u));
}
__device__ __forceinline__ ull fma2(ull a, ull b, ull c) {
    ull d;
    asm("fma.rn.f32x2 %0, %1, %2, %3;" : "=l"(d) : "l"(a), "l"(b), "l"(c));
    return d;
}
__device__ __forceinline__ ull add2(ull a, ull b) {
    ull d;
    asm("add.rn.f32x2 %0, %1, %2;" : "=l"(d) : "l"(a), "l"(b));
    return d;
}

// tanh(x) = 1 - 2/(e^{2x}+1); ex2 + rcp.approx + one FFMA tail.
__device__ __forceinline__ float tanh_fast(float x) {
    float e;
    asm("ex2.approx.f32 %0, %1;" : "=f"(e) : "f"(x * 2.8853900817779268f)); // 2*log2(e)
    float d = e + 1.0f;
    float r;
    asm("rcp.approx.f32 %0, %1;" : "=f"(r) : "f"(d));
    return fmaf(-2.0f, r, 1.0f);
}

__device__ __forceinline__ uint32_t smem_u32(const void* p) {
    return (uint32_t)__cvta_generic_to_shared(p);
}
__device__ __forceinline__ void cp_async16(uint32_t dst, const void* src) {
    asm volatile("cp.async.ca.shared.global [%0], [%1], 16;\n"
                 :: "r"(dst), "l"(src));
}
__device__ __forceinline__ void cp_commit() {
    asm volatile("cp.async.commit_group;\n" ::: "memory");
}
__device__ __forceinline__ void cp_wait_all() {
    asm volatile("cp.async.wait_group 0;\n" ::: "memory");
}

// ---------------------------------------------------------------------------
// Fused kernel: pre-projection + recurrence.
//   h_s = tanh( (x_s . W_ih[t]) + b_ih[t] + b_hh[t] + W_hh[t] . h_{s-1} )
// One chain per 64-thread block (2 warps). Steps processed in chunks of 16:
//   - x chunk (2 KB) streamed in via cp.async double buffer (fully overlapped)
//   - pre[k] (k=0..15) computed into registers before the serial loop
//   - serial loop touches ONLY smem: 16 broadcast LDS.128 (prev h row),
//     32 FFMA2, packed add2 tree, tanh, 1 STS, 2-warp __syncthreads
//   - hidden rows written back per chunk with coalesced STG.128
// ---------------------------------------------------------------------------
__global__ void __launch_bounds__(64, 1) rnn_fused_kernel(
    const float* __restrict__ x,
    const float* __restrict__ W_ih,
    const float* __restrict__ b_ih,
    const float* __restrict__ W_hh,
    const float* __restrict__ b_hh,
    float* __restrict__ hid,
    float* __restrict__ h_last)
{
    const int t = threadIdx.x;               // 0..63, owns h[t]
    const int chain = blockIdx.x;

    __shared__ float4 xbuf[2][CHUNK * 8];    // 2 x 16 rows x 32 floats = 4 KB
    __shared__ float4 hbuf[CHUNK * 16];      // 16 rows x 64 floats = 4 KB (circular)

    // W_hh row t -> 32 f32x2 pairs; W_ih row t -> 16 pairs.
    ull whh[32];
#pragma unroll
    for (int i = 0; i < 16; i++) {
        float4 v = __ldg((const float4*)(W_hh + t * HDIM) + i);
        whh[2 * i]     = f2ull(v.x, v.y);
        whh[2 * i + 1] = f2ull(v.z, v.w);
    }
    ull wih[16];
#pragma unroll
    for (int i = 0; i < 8; i++) {
        float4 v = __ldg((const float4*)(W_ih + t * IDIM) + i);
        wih[2 * i]     = f2ull(v.x, v.y);
        wih[2 * i + 1] = f2ull(v.z, v.w);
    }
    const float bias = __ldg(b_ih + t) + __ldg(b_hh + t);

    // h_{-1} = 0 lives in circular row 15.
    if (t < 16) hbuf[15 * 16 + t] = make_float4(0.f, 0.f, 0.f, 0.f);

    const float* xg0 = x + (size_t)chain * (S_LEN * IDIM);
    float*       hg0 = hid + (size_t)chain * (S_LEN * HDIM);

    // Prologue: stream chunk 0.
    {
        const float4* src = (const float4*)xg0;
        uint32_t dst = smem_u32(&xbuf[0][0]);
        cp_async16(dst + (uint32_t)t * 16,        src + t);
        cp_async16(dst + (uint32_t)(t + 64) * 16, src + t + 64);
        cp_commit();
    }

    float hv = 0.f;

    for (int c = 0; c < NCHUNK; c++) {
        const int cb = c & 1;
        cp_wait_all();
        __syncthreads();                     // xbuf[cb] ready for all threads

        // Stream next chunk into the other buffer (overlaps this chunk).
        if (c + 1 < NCHUNK) {
            const float4* src = (const float4*)(xg0 + (size_t)(c + 1) * (CHUNK * IDIM));
            uint32_t dst = smem_u32(&xbuf[cb ^ 1][0]);
            cp_async16(dst + (uint32_t)t * 16,        src + t);
            cp_async16(dst + (uint32_t)(t + 64) * 16, src + t + 64);
            cp_commit();
        }

        // pre[k] = bias + x_k . W_ih[t]  (registers)
        float p[CHUNK];
#pragma unroll
        for (int k = 0; k < CHUNK; k++) {
            const float4* xp = &xbuf[cb][k * 8];
            float4 v0 = xp[0], v1 = xp[1], v2 = xp[2], v3 = xp[3];
            float4 v4 = xp[4], v5 = xp[5], v6 = xp[6], v7 = xp[7];
            ull a0 = f2ull(bias, 0.f), a1 = 0, a2 = 0, a3 = 0;
            a0 = fma2(f2ull(v0.x, v0.y), wih[0],  a0);
            a1 = fma2(f2ull(v0.z, v0.w), wih[1],  a1);
            a2 = fma2(f2ull(v1.x, v1.y), wih[2],  a2);
            a3 = fma2(f2ull(v1.z, v1.w), wih[3],  a3);
            a0 = fma2(f2ull(v2.x, v2.y), wih[4],  a0);
            a1 = fma2(f2ull(v2.z, v2.w), wih[5],  a1);
            a2 = fma2(f2ull(v3.x, v3.y), wih[6],  a2);
            a3 = fma2(f2ull(v3.z, v3.w), wih[7],  a3);
            a0 = fma2(f2ull(v4.x, v4.y), wih[8],  a0);
            a1 = fma2(f2ull(v4.z, v4.w), wih[9],  a1);
            a2 = fma2(f2ull(v5.x, v5.y), wih[10], a2);
            a3 = fma2(f2ull(v5.z, v5.w), wih[11], a3);
            a0 = fma2(f2ull(v6.x, v6.y), wih[12], a0);
            a1 = fma2(f2ull(v6.z, v6.w), wih[13], a1);
            a2 = fma2(f2ull(v7.x, v7.y), wih[14], a2);
            a3 = fma2(f2ull(v7.z, v7.w), wih[15], a3);
            ull u = add2(add2(a0, a1), add2(a2, a3));
            float lo, hi;
            ull2f(u, lo, hi);
            p[k] = lo + hi;
        }

        // Serial recurrence: 16 steps, all-SMEM critical path.
#pragma unroll
        for (int k = 0; k < CHUNK; k++) {
            const float4* pc = &hbuf[((k + 15) & 15) * 16];

            ull a0 = f2ull(p[k], 0.f), a1 = 0, a2 = 0, a3 = 0,
                a4 = 0, a5 = 0, a6 = 0, a7 = 0;
            {
                float4 v0 = pc[0], v1 = pc[1], v2 = pc[2], v3 = pc[3];
                float4 v4 = pc[4], v5 = pc[5], v6 = pc[6], v7 = pc[7];
                a0 = fma2(f2ull(v0.x, v0.y), whh[0],  a0);
                a1 = fma2(f2ull(v0.z, v0.w), whh[1],  a1);
                a2 = fma2(f2ull(v1.x, v1.y), whh[2],  a2);
                a3 = fma2(f2ull(v1.z, v1.w), whh[3],  a3);
                a4 = fma2(f2ull(v2.x, v2.y), whh[4],  a4);
                a5 = fma2(f2ull(v2.z, v2.w), whh[5],  a5);
                a6 = fma2(f2ull(v3.x, v3.y), whh[6],  a6);
                a7 = fma2(f2ull(v3.z, v3.w), whh[7],  a7);
                a0 = fma2(f2ull(v4.x, v4.y), whh[8],  a0);
                a1 = fma2(f2ull(v4.z, v4.w), whh[9],  a1);
                a2 = fma2(f2ull(v5.x, v5.y), whh[10], a2);
                a3 = fma2(f2ull(v5.z, v5.w), whh[11], a3);
                a4 = fma2(f2ull(v6.x, v6.y), whh[12], a4);
                a5 = fma2(f2ull(v6.z, v6.w), whh[13], a5);
                a6 = fma2(f2ull(v7.x, v7.y), whh[14], a6);
                a7 = fma2(f2ull(v7.z, v7.w), whh[15], a7);
            }
            {
                float4 v0 = pc[8],  v1 = pc[9],  v2 = pc[10], v3 = pc[11];
                float4 v4 = pc[12], v5 = pc[13], v6 = pc[14], v7 = pc[15];
                a0 = fma2(f2ull(v0.x, v0.y), whh[16], a0);
                a1 = fma2(f2ull(v0.z, v0.w), whh[17], a1);
                a2 = fma2(f2ull(v1.x, v1.y), whh[18], a2);
                a3 = fma2(f2ull(v1.z, v1.w), whh[19], a3);
                a4 = fma2(f2ull(v2.x, v2.y), whh[20], a4);
                a5 = fma2(f2ull(v2.z, v2.w), whh[21], a5);
                a6 = fma2(f2ull(v3.x, v3.y), whh[22], a6);
                a7 = fma2(f2ull(v3.z, v3.w), whh[23], a7);
                a0 = fma2(f2ull(v4.x, v4.y), whh[24], a0);
                a1 = fma2(f2ull(v4.z, v4.w), whh[25], a1);
                a2 = fma2(f2ull(v5.x, v5.y), whh[26], a2);
                a3 = fma2(f2ull(v5.z, v5.w), whh[27], a3);
                a4 = fma2(f2ull(v6.x, v6.y), whh[28], a4);
                a5 = fma2(f2ull(v6.z, v6.w), whh[29], a5);
                a6 = fma2(f2ull(v7.x, v7.y), whh[30], a6);
                a7 = fma2(f2ull(v7.z, v7.w), whh[31], a7);
            }

            ull u = add2(add2(add2(a0, a1), add2(a2, a3)),
                         add2(add2(a4, a5), add2(a6, a7)));
            float lo, hi;
            ull2f(u, lo, hi);
            hv = tanh_fast(lo + hi);

            ((float*)hbuf)[k * 64 + t] = hv;   // publish h row k
            __syncthreads();
        }

        // Write back the 16 hidden rows (coalesced STG.128).
        {
            float4* dst = (float4*)(hg0 + (size_t)c * (CHUNK * HDIM)); // 256 f4
#pragma unroll
            for (int j = 0; j < 4; j++)
                dst[t + j * 64] = hbuf[t + j * 64];
        }
        // Ordering vs next chunk's hbuf writes is provided by the
        // cp_wait_all + __syncthreads at the top of the next iteration.
    }

    h_last[chain * HDIM + t] = hv;
}

// ---------------------------------------------------------------------------
// fc kernel: obs[r,o] = sum_h hidden[r,h]*W_fc[o,h] + b_fc[o]
// 64 rows / block of 256 threads; o = tid&31, 8 rows per thread group.
// ---------------------------------------------------------------------------
__global__ void __launch_bounds__(256) fc_kernel(
    const float* __restrict__ hid,
    const float* __restrict__ W_fc,
    const float* __restrict__ b_fc,
    float* __restrict__ obs)
{
    const int tid = threadIdx.x;
    const int o   = tid & 31;
    const int rq  = tid >> 5;                // 0..7
    const int row0 = blockIdx.x * 64;

    __shared__ float4 hs[64 * 16];           // 64 rows x 64 floats = 16 KB

    const float4* h4 = (const float4*)(hid + (size_t)row0 * HDIM); // 1024 f4
#pragma unroll
    for (int j = 0; j < 4; j++) hs[tid + j * 256] = h4[tid + j * 256];

    ull w2[32];
#pragma unroll
    for (int i = 0; i < 16; i++) {
        float4 v = __ldg((const float4*)(W_fc + o * HDIM) + i);
        w2[2 * i]     = f2ull(v.x, v.y);
        w2[2 * i + 1] = f2ull(v.z, v.w);
    }
    const float bias = __ldg(b_fc + o);
    __syncthreads();

#pragma unroll 2
    for (int rr = 0; rr < 8; rr++) {
        const int r = rq * 8 + rr;
        ull a0 = 0, a1 = 0, a2 = 0, a3 = 0;
#pragma unroll
        for (int i = 0; i < 16; i += 2) {
            float4 v0 = hs[r * 16 + i];
            float4 v1 = hs[r * 16 + i + 1];
            a0 = fma2(f2ull(v0.x, v0.y), w2[2 * i],     a0);
            a1 = fma2(f2ull(v0.z, v0.w), w2[2 * i + 1], a1);
            a2 = fma2(f2ull(v1.x, v1.y), w2[2 * i + 2], a2);
            a3 = fma2(f2ull(v1.z, v1.w), w2[2 * i + 3], a3);
        }
        ull u = add2(add2(a0, a1), add2(a2, a3));
        float lo, hi;
        ull2f(u, lo, hi);
        obs[(size_t)(row0 + r) * ODIM + o] = (lo + hi) + bias;
    }
}

// ---------------------------------------------------------------------------
// Launch. d_out layout: [observations | hidden | h_last], fp32.
// ---------------------------------------------------------------------------
extern "C" void kernel_launch(void* const* d_in, const int* in_sizes, int n_in,
                              void* d_out, int out_size) {
    const float* x    = (const float*)d_in[0];
    const float* W_ih = (const float*)d_in[1];
    const float* b_ih = (const float*)d_in[2];
    const float* W_hh = (const float*)d_in[3];
    const float* b_hh = (const float*)d_in[4];
    const float* W_fc = (const float*)d_in[5];
    const float* b_fc = (const float*)d_in[6];

    float* obs    = (float*)d_out;
    float* hid    = obs + OBS_N;
    float* h_last = hid + HID_N;

    rnn_fused_kernel<<<NCHAIN, 64>>>(x, W_ih, b_ih, W_hh, b_hh, hid, h_last);
    fc_kernel<<<(NCHAIN * S_LEN) / 64, 256>>>(hid, W_fc, b_fc, obs);
}

// round 5
// speedup vs baseline: 3.5288x; 1.7591x over previous
#include <cuda_runtime.h>
#include <cstdint>

// Problem constants
#define S_LEN   2048
#define HDIM    64
#define IDIM    32
#define ODIM    32
#define NCHAIN  256                         // B*P
#define OBS_N   (NCHAIN * S_LEN * ODIM)     // 16,777,216
#define HID_N   (NCHAIN * S_LEN * HDIM)     // 33,554,432
#define CHUNK   16
#define NCHUNK  (S_LEN / CHUNK)             // 128

typedef unsigned long long ull;

// ---------------------------------------------------------------------------
// Packed f32x2 helpers
// ---------------------------------------------------------------------------
__device__ __forceinline__ ull f2ull(float lo, float hi) {
    ull r;
    asm("mov.b64 %0, {%1,%2};" : "=l"(r) : "f"(lo), "f"(hi));
    return r;
}
__device__ __forceinline__ void ull2f(ull u, float& lo, float& hi) {
    asm("mov.b64 {%0,%1}, %2;" : "=f"(lo), "=f"(hi) : "l"(u));
}
__device__ __forceinline__ ull fma2(ull a, ull b, ull c) {
    ull d;
    asm("fma.rn.f32x2 %0, %1, %2, %3;" : "=l"(d) : "l"(a), "l"(b), "l"(c));
    return d;
}
__device__ __forceinline__ ull add2(ull a, ull b) {
    ull d;
    asm("add.rn.f32x2 %0, %1, %2;" : "=l"(d) : "l"(a), "l"(b));
    return d;
}

// tanh(x) = 1 - 2/(e^{2x}+1)
__device__ __forceinline__ float tanh_fast(float x) {
    float e;
    asm("ex2.approx.f32 %0, %1;" : "=f"(e) : "f"(x * 2.8853900817779268f));
    float d = e + 1.0f;
    float r;
    asm("rcp.approx.f32 %0, %1;" : "=f"(r) : "f"(d));
    return fmaf(-2.0f, r, 1.0f);
}

__device__ __forceinline__ uint32_t smem_u32(const void* p) {
    return (uint32_t)__cvta_generic_to_shared(p);
}
__device__ __forceinline__ void cp_async16(uint32_t dst, const void* src) {
    asm volatile("cp.async.ca.shared.global [%0], [%1], 16;\n" :: "r"(dst), "l"(src));
}
__device__ __forceinline__ void cp_commit() {
    asm volatile("cp.async.commit_group;\n" ::: "memory");
}
__device__ __forceinline__ void cp_wait_all() {
    asm volatile("cp.async.wait_group 0;\n" ::: "memory");
}

// ---------------------------------------------------------------------------
// Fully fused kernel. One chain per 64-thread block (2 warps).
//  Warp 0: serial recurrence ONLY. Lane l owns h[2l], h[2l+1]. Per step:
//          16 broadcast LDS.128 (prev h row) + 64 FFMA2 + 2 tanh + STS.64 +
//          __syncwarp. No global memory on the critical path.
//  Warp 1: everything else, one chunk (16 steps) at a time:
//          - cp.async x double-buffer (chunk p+1)
//          - pre-projection for chunk p  -> psm[p&1]  (consumed by w0 next phase)
//          - fc + hidden STG + obs STG for chunk p-2 from hbuf[(p-2)&1]
//  One __syncthreads per chunk phase. Per-warp overloaded register arrays:
//   w0: wreg=W_hh row 2l, wreg2=W_hh row 2l+1
//   w1: wreg=[W_ih row 2l | W_ih row 2l+1], wreg2=W_fc row lane
// ---------------------------------------------------------------------------
__global__ void __launch_bounds__(64, 1) fused_rnn_kernel(
    const float* __restrict__ x,
    const float* __restrict__ W_ih,
    const float* __restrict__ b_ih,
    const float* __restrict__ W_hh,
    const float* __restrict__ b_hh,
    const float* __restrict__ W_fc,
    const float* __restrict__ b_fc,
    float* __restrict__ obs,
    float* __restrict__ hid,
    float* __restrict__ h_last)
{
    const int lane = threadIdx.x & 31;
    const int w    = threadIdx.x >> 5;       // 0 = recurrence, 1 = support
    const int chain = blockIdx.x;

    __shared__ float4 xbuf[2][CHUNK * 8];     // 2 x 2 KB x-chunks
    __shared__ float  psm [2][CHUNK][HDIM];   // pre (bias folded), 8 KB
    __shared__ float  hbufs[2][CHUNK][HDIM];  // hidden rows, 8 KB
    __shared__ float4 zrow[16];               // h_{-1} = 0

    const float* xg = x   + (size_t)chain * (S_LEN * IDIM);
    float*       hg = hid + (size_t)chain * (S_LEN * HDIM);
    float*       og = obs + (size_t)chain * (S_LEN * ODIM);

    // Per-warp overloaded weight registers (64 ull = 128 regs total)
    ull wreg[32], wreg2[32];
    float biasA = 0.f, biasB = 0.f, bfc = 0.f;

    if (w == 0) {
        const int ra = 2 * lane, rb = 2 * lane + 1;
#pragma unroll
        for (int i = 0; i < 16; i++) {
            float4 va = __ldg((const float4*)(W_hh + ra * HDIM) + i);
            float4 vb = __ldg((const float4*)(W_hh + rb * HDIM) + i);
            wreg [2 * i]     = f2ull(va.x, va.y);
            wreg [2 * i + 1] = f2ull(va.z, va.w);
            wreg2[2 * i]     = f2ull(vb.x, vb.y);
            wreg2[2 * i + 1] = f2ull(vb.z, vb.w);
        }
        if (lane < 16) zrow[lane] = make_float4(0.f, 0.f, 0.f, 0.f);
    } else {
        const int ra = 2 * lane, rb = 2 * lane + 1;
#pragma unroll
        for (int i = 0; i < 8; i++) {
            float4 va = __ldg((const float4*)(W_ih + ra * IDIM) + i);
            float4 vb = __ldg((const float4*)(W_ih + rb * IDIM) + i);
            wreg[2 * i]          = f2ull(va.x, va.y);
            wreg[2 * i + 1]      = f2ull(va.z, va.w);
            wreg[16 + 2 * i]     = f2ull(vb.x, vb.y);
            wreg[16 + 2 * i + 1] = f2ull(vb.z, vb.w);
        }
#pragma unroll
        for (int i = 0; i < 16; i++) {
            float4 v = __ldg((const float4*)(W_fc + lane * HDIM) + i);
            wreg2[2 * i]     = f2ull(v.x, v.y);
            wreg2[2 * i + 1] = f2ull(v.z, v.w);
        }
        biasA = __ldg(b_ih + 2 * lane)     + __ldg(b_hh + 2 * lane);
        biasB = __ldg(b_ih + 2 * lane + 1) + __ldg(b_hh + 2 * lane + 1);
        bfc   = __ldg(b_fc + lane);
        // Prologue: stream x chunk 0
        const float4* src = (const float4*)xg;
        uint32_t dst = smem_u32(&xbuf[0][0]);
#pragma unroll
        for (int j = 0; j < 4; j++)
            cp_async16(dst + (uint32_t)(lane + 32 * j) * 16, src + lane + 32 * j);
        cp_commit();
    }
    __syncthreads();

    float hvA = 0.f, hvB = 0.f;

    for (int p = 0; p <= NCHUNK + 1; p++) {
        if (w == 0) {
            if (p >= 1 && p <= NCHUNK) {
                const int c = p - 1;
                const int b = c & 1;
                const float4* prow = (c == 0) ? zrow
                                              : (const float4*)hbufs[b ^ 1][CHUNK - 1];
                const float2* pr2 = (const float2*)psm[b];
#pragma unroll 2
                for (int k = 0; k < CHUNK; k++) {
                    const float2 pr = pr2[k * 32 + lane];
                    ull aA0 = 0, aA1 = 0, aA2 = 0, aA3 = 0;
                    ull aB0 = 0, aB1 = 0, aB2 = 0, aB3 = 0;
#pragma unroll
                    for (int i = 0; i < 16; i += 4) {
                        float4 u0 = prow[i], u1 = prow[i + 1];
                        float4 u2 = prow[i + 2], u3 = prow[i + 3];
                        ull q0 = f2ull(u0.x, u0.y), q1 = f2ull(u0.z, u0.w);
                        ull q2 = f2ull(u1.x, u1.y), q3 = f2ull(u1.z, u1.w);
                        ull q4 = f2ull(u2.x, u2.y), q5 = f2ull(u2.z, u2.w);
                        ull q6 = f2ull(u3.x, u3.y), q7 = f2ull(u3.z, u3.w);
                        aA0 = fma2(q0, wreg [2 * i],     aA0);
                        aB0 = fma2(q0, wreg2[2 * i],     aB0);
                        aA1 = fma2(q1, wreg [2 * i + 1], aA1);
                        aB1 = fma2(q1, wreg2[2 * i + 1], aB1);
                        aA2 = fma2(q2, wreg [2 * i + 2], aA2);
                        aB2 = fma2(q2, wreg2[2 * i + 2], aB2);
                        aA3 = fma2(q3, wreg [2 * i + 3], aA3);
                        aB3 = fma2(q3, wreg2[2 * i + 3], aB3);
                        aA0 = fma2(q4, wreg [2 * i + 4], aA0);
                        aB0 = fma2(q4, wreg2[2 * i + 4], aB0);
                        aA1 = fma2(q5, wreg [2 * i + 5], aA1);
                        aB1 = fma2(q5, wreg2[2 * i + 5], aB1);
                        aA2 = fma2(q6, wreg [2 * i + 6], aA2);
                        aB2 = fma2(q6, wreg2[2 * i + 6], aB2);
                        aA3 = fma2(q7, wreg [2 * i + 7], aA3);
                        aB3 = fma2(q7, wreg2[2 * i + 7], aB3);
                    }
                    ull uA = add2(add2(aA0, aA1), add2(aA2, aA3));
                    ull uB = add2(add2(aB0, aB1), add2(aB2, aB3));
                    float la, ha, lb, hb;
                    ull2f(uA, la, ha); ull2f(uB, lb, hb);
                    hvA = tanh_fast((la + ha) + pr.x);
                    hvB = tanh_fast((lb + hb) + pr.y);
                    ((float2*)hbufs[b][k])[lane] = make_float2(hvA, hvB);
                    __syncwarp();
                    prow = (const float4*)hbufs[b][k];
                }
            }
        } else {
            if (p < NCHUNK) {
                cp_wait_all();                        // x chunk p ready
                if (p + 1 < NCHUNK) {                 // stream chunk p+1
                    const float4* src = (const float4*)(xg + (size_t)(p + 1) * (CHUNK * IDIM));
                    uint32_t dst = smem_u32(&xbuf[(p + 1) & 1][0]);
#pragma unroll
                    for (int j = 0; j < 4; j++)
                        cp_async16(dst + (uint32_t)(lane + 32 * j) * 16, src + lane + 32 * j);
                    cp_commit();
                }
                // pre for chunk p  (outputs h = 2*lane, 2*lane+1)
                const float4* xb = xbuf[p & 1];
                float* pd = psm[p & 1][0];
#pragma unroll 2
                for (int k = 0; k < CHUNK; k++) {
                    float4 u0 = xb[k * 8 + 0], u1 = xb[k * 8 + 1];
                    float4 u2 = xb[k * 8 + 2], u3 = xb[k * 8 + 3];
                    float4 u4 = xb[k * 8 + 4], u5 = xb[k * 8 + 5];
                    float4 u6 = xb[k * 8 + 6], u7 = xb[k * 8 + 7];
                    ull q0 = f2ull(u0.x, u0.y), q1 = f2ull(u0.z, u0.w);
                    ull q2 = f2ull(u1.x, u1.y), q3 = f2ull(u1.z, u1.w);
                    ull q4 = f2ull(u2.x, u2.y), q5 = f2ull(u2.z, u2.w);
                    ull q6 = f2ull(u3.x, u3.y), q7 = f2ull(u3.z, u3.w);
                    ull q8 = f2ull(u4.x, u4.y), q9 = f2ull(u4.z, u4.w);
                    ull qa = f2ull(u5.x, u5.y), qb = f2ull(u5.z, u5.w);
                    ull qc = f2ull(u6.x, u6.y), qd = f2ull(u6.z, u6.w);
                    ull qe = f2ull(u7.x, u7.y), qf = f2ull(u7.z, u7.w);
                    ull aA0 = 0, aA1 = 0, aB0 = 0, aB1 = 0;
                    aA0 = fma2(q0, wreg[0],  aA0); aB0 = fma2(q0, wreg[16], aB0);
                    aA1 = fma2(q1, wreg[1],  aA1); aB1 = fma2(q1, wreg[17], aB1);
                    aA0 = fma2(q2, wreg[2],  aA0); aB0 = fma2(q2, wreg[18], aB0);
                    aA1 = fma2(q3, wreg[3],  aA1); aB1 = fma2(q3, wreg[19], aB1);
                    aA0 = fma2(q4, wreg[4],  aA0); aB0 = fma2(q4, wreg[20], aB0);
                    aA1 = fma2(q5, wreg[5],  aA1); aB1 = fma2(q5, wreg[21], aB1);
                    aA0 = fma2(q6, wreg[6],  aA0); aB0 = fma2(q6, wreg[22], aB0);
                    aA1 = fma2(q7, wreg[7],  aA1); aB1 = fma2(q7, wreg[23], aB1);
                    aA0 = fma2(q8, wreg[8],  aA0); aB0 = fma2(q8, wreg[24], aB0);
                    aA1 = fma2(q9, wreg[9],  aA1); aB1 = fma2(q9, wreg[25], aB1);
                    aA0 = fma2(qa, wreg[10], aA0); aB0 = fma2(qa, wreg[26], aB0);
                    aA1 = fma2(qb, wreg[11], aA1); aB1 = fma2(qb, wreg[27], aB1);
                    aA0 = fma2(qc, wreg[12], aA0); aB0 = fma2(qc, wreg[28], aB0);
                    aA1 = fma2(qd, wreg[13], aA1); aB1 = fma2(qd, wreg[29], aB1);
                    aA0 = fma2(qe, wreg[14], aA0); aB0 = fma2(qe, wreg[30], aB0);
                    aA1 = fma2(qf, wreg[15], aA1); aB1 = fma2(qf, wreg[31], aB1);
                    ull uA = add2(aA0, aA1), uB = add2(aB0, aB1);
                    float la, ha, lb, hb;
                    ull2f(uA, la, ha); ull2f(uB, lb, hb);
                    ((float2*)(pd + k * HDIM))[lane] =
                        make_float2((la + ha) + biasA, (lb + hb) + biasB);
                }
            }
            if (p >= 2) {
                const int q  = p - 2;
                const int bq = q & 1;
                // hidden write-back (coalesced STG.128)
                const float4* hsrc = (const float4*)hbufs[bq];
                float4* hdst = (float4*)(hg + (size_t)q * (CHUNK * HDIM));
#pragma unroll
                for (int j = 0; j < 8; j++)
                    hdst[lane + 32 * j] = hsrc[lane + 32 * j];
                // fc: obs[row][lane]
                float* od = og + (size_t)q * (CHUNK * ODIM);
#pragma unroll 2
                for (int rr = 0; rr < CHUNK; rr++) {
                    const float4* hv4 = (const float4*)hbufs[bq][rr];
                    ull a0 = 0, a1 = 0, a2 = 0, a3 = 0;
#pragma unroll
                    for (int i = 0; i < 16; i += 4) {
                        float4 u0 = hv4[i], u1 = hv4[i + 1];
                        float4 u2 = hv4[i + 2], u3 = hv4[i + 3];
                        a0 = fma2(f2ull(u0.x, u0.y), wreg2[2 * i],     a0);
                        a1 = fma2(f2ull(u0.z, u0.w), wreg2[2 * i + 1], a1);
                        a2 = fma2(f2ull(u1.x, u1.y), wreg2[2 * i + 2], a2);
                        a3 = fma2(f2ull(u1.z, u1.w), wreg2[2 * i + 3], a3);
                        a0 = fma2(f2ull(u2.x, u2.y), wreg2[2 * i + 4], a0);
                        a1 = fma2(f2ull(u2.z, u2.w), wreg2[2 * i + 5], a1);
                        a2 = fma2(f2ull(u3.x, u3.y), wreg2[2 * i + 6], a2);
                        a3 = fma2(f2ull(u3.z, u3.w), wreg2[2 * i + 7], a3);
                    }
                    ull u = add2(add2(a0, a1), add2(a2, a3));
                    float lo, hi;
                    ull2f(u, lo, hi);
                    od[rr * ODIM + lane] = (lo + hi) + bfc;
                }
            }
        }
        __syncthreads();
    }

    if (w == 0) {
        ((float2*)(h_last + chain * HDIM))[lane] = make_float2(hvA, hvB);
    }
}

// ---------------------------------------------------------------------------
// Launch. d_out layout: [observations | hidden | h_last], fp32.
// ---------------------------------------------------------------------------
extern "C" void kernel_launch(void* const* d_in, const int* in_sizes, int n_in,
                              void* d_out, int out_size) {
    const float* x    = (const float*)d_in[0];
    const float* W_ih = (const float*)d_in[1];
    const float* b_ih = (const float*)d_in[2];
    const float* W_hh = (const float*)d_in[3];
    const float* b_hh = (const float*)d_in[4];
    const float* W_fc = (const float*)d_in[5];
    const float* b_fc = (const float*)d_in[6];

    float* obs    = (float*)d_out;
    float* hid    = obs + OBS_N;
    float* h_last = hid + HID_N;

    fused_rnn_kernel<<<NCHAIN, 64>>>(x, W_ih, b_ih, W_hh, b_hh, W_fc, b_fc,
                                     obs, hid, h_last);
}